// round 15
// baseline (speedup 1.0000x reference)
#include <cuda_runtime.h>
#include <math.h>
#include <stdint.h>

// HopAttentionLayer: B=256, T=64, N=2048, D=128
// attention[b,n] = softmax_n( 64 * <context[b,n,:], W[128:256]> )
// out[b,n,d] = attention[b,n] * context[b,n,d]
//
// Cluster-of-8 (128KB slice per CTA), 6 CTAs/SM (BDIM=256, launch_bounds(256,6),
// 37KB dummy dynamic SMEM). Six co-resident CTAs belong to six DIFFERENT
// clusters, so their read/softmax/write phases interleave and DRAM stays busy.
// Pass 1 reads the slice (allocates in L2; live read footprint 6*148*128KB =
// 111MB < 126MB LTS). One DSMEM exchange for global softmax stats with a split
// second barrier (arrive after gather, wait at exit). Pass 2 re-reads from L2,
// streams output with evict-first stores. DRAM traffic = 536 MB floor.

#define BDIM 256
static constexpr int Bsz  = 256;
static constexpr int Nctx = 2048;
static constexpr int Dd   = 128;
static constexpr int CS   = 8;            // CTAs per batch (cluster)
static constexpr int RS   = Nctx / CS;    // 256 rows per CTA (== BDIM)
static constexpr int NWARP = BDIM / 32;   // 8

// dynamic smem: first few floats used, rest pads occupancy to 6 CTAs/SM
static constexpr int OFF_SCORE = 0;                 // RS = 256
static constexpr int OFF_RED   = OFF_SCORE + RS;    // NWARP = 8
static constexpr int OFF_PUB   = OFF_RED + NWARP;   // 2 (lmax, lsum)
static constexpr int OFF_GLB   = OFF_PUB + 2;       // 2 (gmax, ginv)
static constexpr size_t SMEM_BYTES = 37 * 1024;     // 6 x 37KB = 222KB <= 228KB

__device__ __forceinline__ uint32_t smem_u32(const void* p) {
    uint32_t a;
    asm("{ .reg .u64 t; cvta.to.shared.u64 t, %1; cvt.u32.u64 %0, t; }"
        : "=r"(a) : "l"(p));
    return a;
}
__device__ __forceinline__ float dsmem_ld_f32(uint32_t laddr, uint32_t rank) {
    uint32_t ra;
    asm("mapa.shared::cluster.u32 %0, %1, %2;" : "=r"(ra) : "r"(laddr), "r"(rank));
    float v;
    asm volatile("ld.shared::cluster.f32 %0, [%1];" : "=f"(v) : "r"(ra));
    return v;
}
#define CLUSTER_ARRIVE() asm volatile("barrier.cluster.arrive.aligned;" ::: "memory")
#define CLUSTER_WAIT()   asm volatile("barrier.cluster.wait.aligned;"   ::: "memory")

__global__ __launch_bounds__(BDIM, 6) __cluster_dims__(CS, 1, 1)
void hop_attn_l2(const float* __restrict__ ctx,
                 const float* __restrict__ W,
                 float* __restrict__ out)
{
    extern __shared__ float sm[];
    float* s_score = sm + OFF_SCORE;
    float* s_red   = sm + OFF_RED;
    float* s_pub   = sm + OFF_PUB;
    float* s_glb   = sm + OFF_GLB;

    const int rank  = blockIdx.x;
    const int batch = blockIdx.y;
    const int tid   = threadIdx.x;
    const int warp  = tid >> 5;
    const int lane  = tid & 31;

    const float4 wc = *reinterpret_cast<const float4*>(W + Dd + lane * 4);

    const float4* c4 = reinterpret_cast<const float4*>(ctx)
                     + ((size_t)batch * Nctx + rank * RS) * (Dd / 4);
    float4*       o4 = reinterpret_cast<float4*>(out)
                     + ((size_t)batch * Nctx + rank * RS) * (Dd / 4);

    // ---- Pass 1: scores (32 rows per warp, compiler batches the loads) ----
    #pragma unroll 4
    for (int k = 0; k < RS / NWARP; k++) {           // 32 iters
        const int row = k * NWARP + warp;            // contiguous 4KB window/step
        float4 v = c4[row * (Dd / 4) + lane];
        float d = v.x * wc.x + v.y * wc.y + v.z * wc.z + v.w * wc.w;
        #pragma unroll
        for (int o = 16; o; o >>= 1) d += __shfl_xor_sync(0xffffffffu, d, o);
        if (lane == 0) s_score[row] = 64.0f * d;     // fold T=64
    }
    __syncthreads();

    // ---- Local max over RS=256 scores (exactly one per thread) ----
    float m = s_score[tid];
    #pragma unroll
    for (int o = 16; o; o >>= 1) m = fmaxf(m, __shfl_xor_sync(0xffffffffu, m, o));
    if (lane == 0) s_red[warp] = m;
    __syncthreads();
    if (warp == 0) {
        float mm = (lane < NWARP) ? s_red[lane] : -INFINITY;
        #pragma unroll
        for (int o = 4; o; o >>= 1) mm = fmaxf(mm, __shfl_xor_sync(0xffffffffu, mm, o));
        if (lane == 0) s_pub[0] = mm;
    }
    __syncthreads();
    const float lmax = s_pub[0];

    // ---- Local sum of exp(score - lmax) ----
    float e = __expf(s_score[tid] - lmax);
    float sum = e;
    #pragma unroll
    for (int o = 16; o; o >>= 1) sum += __shfl_xor_sync(0xffffffffu, sum, o);
    if (lane == 0) s_red[warp] = sum;
    __syncthreads();
    if (warp == 0) {
        float ss = (lane < NWARP) ? s_red[lane] : 0.0f;
        #pragma unroll
        for (int o = 4; o; o >>= 1) ss += __shfl_xor_sync(0xffffffffu, ss, o);
        if (lane == 0) s_pub[1] = ss;
    }
    // Publish (lmax, lsum): full barrier #1 (all ranks' s_pub must be visible).
    CLUSTER_ARRIVE();
    CLUSTER_WAIT();

    // ---- Gather (m_i, s_i) from all 8 ranks; combine ----
    if (warp == 0) {
        const uint32_t aM = smem_u32(&s_pub[0]);
        const uint32_t aS = smem_u32(&s_pub[1]);
        float mi = -INFINITY, si = 0.0f;
        if (lane < CS) { mi = dsmem_ld_f32(aM, lane); si = dsmem_ld_f32(aS, lane); }
        float gm = mi;
        #pragma unroll
        for (int o = 4; o; o >>= 1) gm = fmaxf(gm, __shfl_xor_sync(0xffffffffu, gm, o));
        float contrib = (lane < CS) ? si * __expf(mi - gm) : 0.0f;
        #pragma unroll
        for (int o = 4; o; o >>= 1) contrib += __shfl_xor_sync(0xffffffffu, contrib, o);
        if (lane == 0) { s_glb[0] = gm; s_glb[1] = 1.0f / contrib; }
    }
    __syncthreads();           // gather done within CTA
    CLUSTER_ARRIVE();          // barrier #2 arrive: "done reading peer SMEM"
                               // (wait deferred to kernel end — overlaps pass 2)
    const float gmax = s_glb[0];
    const float ginv = s_glb[1];

    // ---- Finalize probs in SMEM (e already holds exp(score - lmax)) ----
    s_score[tid] = e * __expf(lmax - gmax) * ginv;
    __syncthreads();

    // ---- Pass 2: re-read slice (L2 hit), scale, streaming store ----
    constexpr int NV4 = RS * (Dd / 4);   // 8192 float4
    #pragma unroll 4
    for (int i = 0; i < NV4 / BDIM; i++) {   // 32 iters
        const int idx = i * BDIM + tid;
        const float a = s_score[idx >> 5];   // 32 float4 per row -> uniform per warp
        float4 v = c4[idx];
        v.x *= a; v.y *= a; v.z *= a; v.w *= a;
        __stcs(&o4[idx], v);                 // evict-first: protect cached reads
    }

    CLUSTER_WAIT();   // usually satisfied long ago — near-free
}

extern "C" void kernel_launch(void* const* d_in, const int* in_sizes, int n_in,
                              void* d_out, int out_size)
{
    // d_in[0]=targetsentence_emb (unused), d_in[1]=context_emb, d_in[2]=W, d_in[3]=b (unused)
    const float* ctx = (const float*)d_in[1];
    const float* W   = (const float*)d_in[2];
    float* out       = (float*)d_out;

    cudaFuncSetAttribute(hop_attn_l2,
                         cudaFuncAttributeMaxDynamicSharedMemorySize,
                         (int)SMEM_BYTES);
    hop_attn_l2<<<dim3(CS, Bsz, 1), BDIM, SMEM_BYTES>>>(ctx, W, out);
}

// round 17
// speedup vs baseline: 1.2505x; 1.2505x over previous
#include <cuda_runtime.h>
#include <math.h>
#include <stdint.h>

// HopAttentionLayer: B=256, T=64, N=2048, D=128
// attention[b,n] = softmax_n( 64 * <context[b,n,:], W[128:256]> )
// out[b,n,d] = attention[b,n] * context[b,n,d]
//
// Cluster-of-8 (128KB slice per CTA), 5 CTAs/SM (BDIM=256, launch_bounds(256,5),
// 45KB dummy dynamic SMEM). Five co-resident CTAs belong to five DIFFERENT
// clusters -> read/softmax/write phases interleave, DRAM stays busy.
// Read footprint 5*148*128KB = 92.5MB < 126MB LTS -> pass-2 re-read hits L2.
// Pass-2 reads are last-use (__ldlu, evict after read) and run in REVERSE
// order (youngest lines first) to protect the L2 margin. Output written with
// evict-first stores. DRAM traffic ~ 536 MB floor.

#define BDIM 256
static constexpr int Bsz  = 256;
static constexpr int Nctx = 2048;
static constexpr int Dd   = 128;
static constexpr int CS   = 8;            // CTAs per batch (cluster)
static constexpr int RS   = Nctx / CS;    // 256 rows per CTA (== BDIM)
static constexpr int NWARP = BDIM / 32;   // 8

// dynamic smem: first few floats used, rest pads occupancy to 5 CTAs/SM
static constexpr int OFF_SCORE = 0;                 // RS = 256
static constexpr int OFF_RED   = OFF_SCORE + RS;    // NWARP = 8
static constexpr int OFF_PUB   = OFF_RED + NWARP;   // 2 (lmax, lsum)
static constexpr int OFF_GLB   = OFF_PUB + 2;       // 2 (gmax, ginv)
static constexpr size_t SMEM_BYTES = 45 * 1024;     // 5 x 45KB = 225KB <= 228KB

__device__ __forceinline__ uint32_t smem_u32(const void* p) {
    uint32_t a;
    asm("{ .reg .u64 t; cvta.to.shared.u64 t, %1; cvt.u32.u64 %0, t; }"
        : "=r"(a) : "l"(p));
    return a;
}
__device__ __forceinline__ float dsmem_ld_f32(uint32_t laddr, uint32_t rank) {
    uint32_t ra;
    asm("mapa.shared::cluster.u32 %0, %1, %2;" : "=r"(ra) : "r"(laddr), "r"(rank));
    float v;
    asm volatile("ld.shared::cluster.f32 %0, [%1];" : "=f"(v) : "r"(ra));
    return v;
}
#define CLUSTER_ARRIVE() asm volatile("barrier.cluster.arrive.aligned;" ::: "memory")
#define CLUSTER_WAIT()   asm volatile("barrier.cluster.wait.aligned;"   ::: "memory")

__global__ __launch_bounds__(BDIM, 5) __cluster_dims__(CS, 1, 1)
void hop_attn_l2(const float* __restrict__ ctx,
                 const float* __restrict__ W,
                 float* __restrict__ out)
{
    extern __shared__ float sm[];
    float* s_score = sm + OFF_SCORE;
    float* s_red   = sm + OFF_RED;
    float* s_pub   = sm + OFF_PUB;
    float* s_glb   = sm + OFF_GLB;

    const int rank  = blockIdx.x;
    const int batch = blockIdx.y;
    const int tid   = threadIdx.x;
    const int warp  = tid >> 5;
    const int lane  = tid & 31;

    const float4 wc = *reinterpret_cast<const float4*>(W + Dd + lane * 4);

    const float4* c4 = reinterpret_cast<const float4*>(ctx)
                     + ((size_t)batch * Nctx + rank * RS) * (Dd / 4);
    float4*       o4 = reinterpret_cast<float4*>(out)
                     + ((size_t)batch * Nctx + rank * RS) * (Dd / 4);

    // ---- Pass 1: scores (32 rows per warp; loads allocate in L2) ----
    #pragma unroll 4
    for (int k = 0; k < RS / NWARP; k++) {           // 32 iters
        const int row = k * NWARP + warp;            // contiguous 4KB window/step
        float4 v = c4[row * (Dd / 4) + lane];
        float d = v.x * wc.x + v.y * wc.y + v.z * wc.z + v.w * wc.w;
        #pragma unroll
        for (int o = 16; o; o >>= 1) d += __shfl_xor_sync(0xffffffffu, d, o);
        if (lane == 0) s_score[row] = 64.0f * d;     // fold T=64
    }
    __syncthreads();

    // ---- Local max over RS=256 scores (exactly one per thread) ----
    float m = s_score[tid];
    #pragma unroll
    for (int o = 16; o; o >>= 1) m = fmaxf(m, __shfl_xor_sync(0xffffffffu, m, o));
    if (lane == 0) s_red[warp] = m;
    __syncthreads();
    if (warp == 0) {
        float mm = (lane < NWARP) ? s_red[lane] : -INFINITY;
        #pragma unroll
        for (int o = 4; o; o >>= 1) mm = fmaxf(mm, __shfl_xor_sync(0xffffffffu, mm, o));
        if (lane == 0) s_pub[0] = mm;
    }
    __syncthreads();
    const float lmax = s_pub[0];

    // ---- Local sum of exp(score - lmax) ----
    float e = __expf(s_score[tid] - lmax);
    float sum = e;
    #pragma unroll
    for (int o = 16; o; o >>= 1) sum += __shfl_xor_sync(0xffffffffu, sum, o);
    if (lane == 0) s_red[warp] = sum;
    __syncthreads();
    if (warp == 0) {
        float ss = (lane < NWARP) ? s_red[lane] : 0.0f;
        #pragma unroll
        for (int o = 4; o; o >>= 1) ss += __shfl_xor_sync(0xffffffffu, ss, o);
        if (lane == 0) s_pub[1] = ss;
    }
    // Publish (lmax, lsum): full barrier #1 (all ranks' s_pub must be visible).
    CLUSTER_ARRIVE();
    CLUSTER_WAIT();

    // ---- Gather (m_i, s_i) from all 8 ranks; combine ----
    if (warp == 0) {
        const uint32_t aM = smem_u32(&s_pub[0]);
        const uint32_t aS = smem_u32(&s_pub[1]);
        float mi = -INFINITY, si = 0.0f;
        if (lane < CS) { mi = dsmem_ld_f32(aM, lane); si = dsmem_ld_f32(aS, lane); }
        float gm = mi;
        #pragma unroll
        for (int o = 4; o; o >>= 1) gm = fmaxf(gm, __shfl_xor_sync(0xffffffffu, gm, o));
        float contrib = (lane < CS) ? si * __expf(mi - gm) : 0.0f;
        #pragma unroll
        for (int o = 4; o; o >>= 1) contrib += __shfl_xor_sync(0xffffffffu, contrib, o);
        if (lane == 0) { s_glb[0] = gm; s_glb[1] = 1.0f / contrib; }
    }
    __syncthreads();           // gather done within CTA
    CLUSTER_ARRIVE();          // barrier #2 arrive: "done reading peer SMEM"
                               // (wait deferred to kernel end — overlaps pass 2)
    const float gmax = s_glb[0];
    const float ginv = s_glb[1];

    // ---- Finalize probs in SMEM (e already holds exp(score - lmax)) ----
    s_score[tid] = e * __expf(lmax - gmax) * ginv;
    __syncthreads();

    // ---- Pass 2: re-read slice from L2 (last-use, reverse order), scale,
    //      streaming store ----
    constexpr int NV4 = RS * (Dd / 4);   // 8192 float4
    #pragma unroll 4
    for (int i = NV4 / BDIM - 1; i >= 0; i--) {   // 32 iters, youngest lines first
        const int idx = i * BDIM + tid;
        const float a = s_score[idx >> 5];        // uniform per warp
        float4 v = __ldlu(&c4[idx]);              // last-use: evict after read
        v.x *= a; v.y *= a; v.z *= a; v.w *= a;
        __stcs(&o4[idx], v);                      // evict-first store
    }

    CLUSTER_WAIT();   // usually satisfied long ago — near-free
}

extern "C" void kernel_launch(void* const* d_in, const int* in_sizes, int n_in,
                              void* d_out, int out_size)
{
    // d_in[0]=targetsentence_emb (unused), d_in[1]=context_emb, d_in[2]=W, d_in[3]=b (unused)
    const float* ctx = (const float*)d_in[1];
    const float* W   = (const float*)d_in[2];
    float* out       = (float*)d_out;

    cudaFuncSetAttribute(hop_attn_l2,
                         cudaFuncAttributeMaxDynamicSharedMemorySize,
                         (int)SMEM_BYTES);
    hop_attn_l2<<<dim3(CS, Bsz, 1), BDIM, SMEM_BYTES>>>(ctx, W, out);
}